// round 2
// baseline (speedup 1.0000x reference)
#include <cuda_runtime.h>
#include <cstdint>
#include <cstddef>

#define NB 8
#define HW 4096
#define CI 256
#define DQ 64

// scratch (device globals -- no allocation allowed)
__device__ float g_Q[(size_t)NB * HW * DQ];    // tf32-rounded, pre-scaled by sqrt(log2 e)
__device__ float g_rZ[NB * HW];                // 1 / softmax row sum
__device__ float g_att[(size_t)NB * CI * HW];  // att in (C, HW)-linear layout per batch

static __device__ __forceinline__ float to_tf32(float x) {
    unsigned r; asm("cvt.rna.tf32.f32 %0, %1;" : "=r"(r) : "f"(x));
    return __uint_as_float(r);
}
static __device__ __forceinline__ float ex2f(float x) {
    float y; asm("ex2.approx.ftz.f32 %0, %1;" : "=f"(y) : "f"(x));
    return y;
}
static __device__ __forceinline__ void mma8(float c[4], unsigned a0, unsigned a1, unsigned a2,
                                            unsigned a3, unsigned b0, unsigned b1) {
    asm volatile(
        "mma.sync.aligned.m16n8k8.row.col.f32.tf32.tf32.f32 "
        "{%0,%1,%2,%3},{%4,%5,%6,%7},{%8,%9},{%0,%1,%2,%3};"
        : "+f"(c[0]), "+f"(c[1]), "+f"(c[2]), "+f"(c[3])
        : "r"(a0), "r"(a1), "r"(a2), "r"(a3), "r"(b0), "r"(b1));
}
#define FU __float_as_uint

// ---------------------------------------------------------------------------
// K1: Q = (F @ W) * sqrt(log2 e), fp32 FMA, tf32-rounded on store.
// Block 256 threads: 128(p) x 64(d) tile, K=256 in chunks of 32.
// ---------------------------------------------------------------------------
__global__ __launch_bounds__(256) void k_query(const float* __restrict__ F,
                                               const float* __restrict__ W) {
    __shared__ float A_s[32][132];  // F chunk, transposed [k][p]
    __shared__ float W_s[32][68];   // W chunk [k][d]
    const int tid = threadIdx.x;
    const int n = blockIdx.y, p0 = blockIdx.x * 128;
    const int tx = tid & 15, ty = tid >> 4;  // cols 4*tx.., rows 8*ty..
    float acc[8][4];
#pragma unroll
    for (int i = 0; i < 8; i++)
#pragma unroll
        for (int j = 0; j < 4; j++) acc[i][j] = 0.f;
    const float* Fb = F + ((size_t)n * HW + p0) * CI;

    for (int kc = 0; kc < 8; kc++) {
        __syncthreads();
#pragma unroll
        for (int i = 0; i < 4; i++) {
            int idx = tid + i * 256;
            int row = idx >> 3, c4 = (idx & 7) * 4;
            float4 v = *(const float4*)(Fb + (size_t)row * CI + kc * 32 + c4);
            A_s[c4 + 0][row] = v.x; A_s[c4 + 1][row] = v.y;
            A_s[c4 + 2][row] = v.z; A_s[c4 + 3][row] = v.w;
        }
#pragma unroll
        for (int i = 0; i < 2; i++) {
            int idx = tid + i * 256;
            int row = idx >> 4, c4 = (idx & 15) * 4;
            *(float4*)&W_s[row][c4] = *(const float4*)(W + (kc * 32 + row) * DQ + c4);
        }
        __syncthreads();
#pragma unroll
        for (int k = 0; k < 32; k++) {
            float4 a0 = *(float4*)&A_s[k][8 * ty];
            float4 a1 = *(float4*)&A_s[k][8 * ty + 4];
            float4 b  = *(float4*)&W_s[k][4 * tx];
            float av[8] = {a0.x, a0.y, a0.z, a0.w, a1.x, a1.y, a1.z, a1.w};
            float bv[4] = {b.x, b.y, b.z, b.w};
#pragma unroll
            for (int i = 0; i < 8; i++)
#pragma unroll
                for (int j = 0; j < 4; j++) acc[i][j] += av[i] * bv[j];
        }
    }
    const float s = 1.2011224087864498f;  // sqrt(log2 e): Q.Q = log2(e) * logit
#pragma unroll
    for (int i = 0; i < 8; i++) {
        int p = p0 + 8 * ty + i;
        float4 o;
        o.x = to_tf32(acc[i][0] * s); o.y = to_tf32(acc[i][1] * s);
        o.z = to_tf32(acc[i][2] * s); o.w = to_tf32(acc[i][3] * s);
        *(float4*)(g_Q + ((size_t)n * HW + p) * DQ + 4 * tx) = o;
    }
}

// ---------------------------------------------------------------------------
// K2: rZ[p] = 1 / sum_q 2^(Q[p].Q[q]).  64 p-rows per block, q streamed in 64s.
// tf32 mma for logits; deterministic reduction (regs + shfl + smem, no atomics).
// ---------------------------------------------------------------------------
__global__ __launch_bounds__(256) void k_rowsum() {
    __shared__ float Qp_s[64][68];
    __shared__ float Qq_s[64][68];
    __shared__ float Zp[8][64];
    const int tid = threadIdx.x, w = tid >> 5, lane = tid & 31;
    const int gid = lane >> 2, t4 = lane & 3;
    const int n = blockIdx.y, p0 = blockIdx.x * 64;
    const int m0 = (w & 3) * 16, nb = (w >> 2) * 32;
    const float* Qb = g_Q + (size_t)n * HW * DQ;

#pragma unroll
    for (int i = 0; i < 4; i++) {
        int idx = tid + i * 256;
        int row = idx >> 4, c4 = (idx & 15) * 4;
        *(float4*)&Qp_s[row][c4] = *(const float4*)(Qb + (size_t)(p0 + row) * DQ + c4);
    }
    float zr0 = 0.f, zr1 = 0.f;
    for (int qc = 0; qc < 64; qc++) {
        __syncthreads();
#pragma unroll
        for (int i = 0; i < 4; i++) {
            int idx = tid + i * 256;
            int row = idx >> 4, c4 = (idx & 15) * 4;
            *(float4*)&Qq_s[row][c4] = *(const float4*)(Qb + (size_t)(qc * 64 + row) * DQ + c4);
        }
        __syncthreads();
        float acc[4][4] = {};
#pragma unroll
        for (int kt = 0; kt < 8; kt++) {
            int k0 = kt * 8;
            unsigned a0 = FU(Qp_s[m0 + gid][k0 + t4]), a1 = FU(Qp_s[m0 + gid + 8][k0 + t4]);
            unsigned a2 = FU(Qp_s[m0 + gid][k0 + t4 + 4]), a3 = FU(Qp_s[m0 + gid + 8][k0 + t4 + 4]);
#pragma unroll
            for (int nt = 0; nt < 4; nt++) {
                unsigned b0 = FU(Qq_s[nb + nt * 8 + gid][k0 + t4]);
                unsigned b1 = FU(Qq_s[nb + nt * 8 + gid][k0 + t4 + 4]);
                mma8(acc[nt], a0, a1, a2, a3, b0, b1);
            }
        }
#pragma unroll
        for (int nt = 0; nt < 4; nt++) {
            zr0 += to_tf32(ex2f(acc[nt][0])) + to_tf32(ex2f(acc[nt][1]));
            zr1 += to_tf32(ex2f(acc[nt][2])) + to_tf32(ex2f(acc[nt][3]));
        }
    }
    zr0 += __shfl_xor_sync(0xffffffffu, zr0, 1);
    zr0 += __shfl_xor_sync(0xffffffffu, zr0, 2);
    zr1 += __shfl_xor_sync(0xffffffffu, zr1, 1);
    zr1 += __shfl_xor_sync(0xffffffffu, zr1, 2);
    if (t4 == 0) { Zp[w][m0 + gid] = zr0; Zp[w][m0 + gid + 8] = zr1; }
    __syncthreads();
    if (tid < 64) {
        int mg = tid >> 4;
        float z = Zp[mg][tid] + Zp[mg + 4][tid];
        g_rZ[n * HW + p0 + tid] = 1.f / z;
    }
}

// ---------------------------------------------------------------------------
// K3: att[q,c] += 2^(Qq.Qp) * G[p,c], G = F * rZ.  Output tile 128q x 128c,
// 512 threads, p streamed in 64s.  att stored (C, HW)-linear.
// ---------------------------------------------------------------------------
#define K3_F_QQ 0
#define K3_F_QP 8704
#define K3_F_E  (8704 + 4352)
#define K3_F_G  (8704 + 4352 + 8704)
#define K3_SMEM ((8704 + 4352 + 8704 + 8704) * 4)

__global__ __launch_bounds__(512, 1) void k_att(const float* __restrict__ F) {
    extern __shared__ float sm[];
    float(*Qq_s)[68]  = (float(*)[68])(sm + K3_F_QQ);   // 128x68
    float(*Qp_s)[68]  = (float(*)[68])(sm + K3_F_QP);   // 64x68
    float(*E_s)[68]   = (float(*)[68])(sm + K3_F_E);    // 128x68
    float(*G_s)[136]  = (float(*)[136])(sm + K3_F_G);   // 64x136
    const int tid = threadIdx.x, w = tid >> 5, lane = tid & 31;
    const int gid = lane >> 2, t4 = lane & 3;
    const int q0 = blockIdx.x * 128, c0 = blockIdx.y * 128, n = blockIdx.z;
    const float* Qb = g_Q + (size_t)n * HW * DQ;
    const float* Fb = F + (size_t)n * HW * CI;
    const float* rZb = g_rZ + n * HW;

#pragma unroll
    for (int i = 0; i < 4; i++) {
        int idx = tid + i * 512;
        int row = idx >> 4, c4 = (idx & 15) * 4;
        *(float4*)&Qq_s[row][c4] = *(const float4*)(Qb + (size_t)(q0 + row) * DQ + c4);
    }
    const int m1 = (w & 7) * 16, n1 = (w >> 3) * 32;   // gemm1 warp tile
    const int wr = (w & 3) * 32, wc = (w >> 2) * 32;   // gemm2 warp tile
    float acc[2][4][4] = {};

    for (int pc = 0; pc < 64; pc++) {
        __syncthreads();
        const int p0 = pc * 64;
#pragma unroll
        for (int i = 0; i < 2; i++) {
            int idx = tid + i * 512;
            int row = idx >> 4, c4 = (idx & 15) * 4;
            *(float4*)&Qp_s[row][c4] = *(const float4*)(Qb + (size_t)(p0 + row) * DQ + c4);
        }
#pragma unroll
        for (int i = 0; i < 4; i++) {
            int idx = tid + i * 512;
            int row = idx >> 5, c4 = (idx & 31) * 4;
            float rz = rZb[p0 + row];
            float4 v = *(const float4*)(Fb + (size_t)(p0 + row) * CI + c0 + c4);
            float4 g;
            g.x = to_tf32(v.x * rz); g.y = to_tf32(v.y * rz);
            g.z = to_tf32(v.z * rz); g.w = to_tf32(v.w * rz);
            *(float4*)&G_s[row][c4] = g;
        }
        __syncthreads();
        // gemm1: S[128 x 64] = Qq @ Qp^T (warp: 16 x 32)
        float s[4][4] = {};
#pragma unroll
        for (int kt = 0; kt < 8; kt++) {
            int k0 = kt * 8;
            unsigned a0 = FU(Qq_s[m1 + gid][k0 + t4]), a1 = FU(Qq_s[m1 + gid + 8][k0 + t4]);
            unsigned a2 = FU(Qq_s[m1 + gid][k0 + t4 + 4]), a3 = FU(Qq_s[m1 + gid + 8][k0 + t4 + 4]);
#pragma unroll
            for (int nt = 0; nt < 4; nt++) {
                unsigned b0 = FU(Qp_s[n1 + nt * 8 + gid][k0 + t4]);
                unsigned b1 = FU(Qp_s[n1 + nt * 8 + gid][k0 + t4 + 4]);
                mma8(s[nt], a0, a1, a2, a3, b0, b1);
            }
        }
#pragma unroll
        for (int nt = 0; nt < 4; nt++) {
            int cb = n1 + nt * 8 + 2 * t4;
            E_s[m1 + gid][cb]         = to_tf32(ex2f(s[nt][0]));
            E_s[m1 + gid][cb + 1]     = to_tf32(ex2f(s[nt][1]));
            E_s[m1 + gid + 8][cb]     = to_tf32(ex2f(s[nt][2]));
            E_s[m1 + gid + 8][cb + 1] = to_tf32(ex2f(s[nt][3]));
        }
        __syncthreads();
        // gemm2: acc += E(128x64) @ G(64x128) (warp: 32 x 32)
#pragma unroll
        for (int kt = 0; kt < 8; kt++) {
            int k0 = kt * 8;
            unsigned b0[4], b1[4];
#pragma unroll
            for (int nt = 0; nt < 4; nt++) {
                b0[nt] = FU(G_s[k0 + t4][wc + nt * 8 + gid]);
                b1[nt] = FU(G_s[k0 + t4 + 4][wc + nt * 8 + gid]);
            }
#pragma unroll
            for (int mt = 0; mt < 2; mt++) {
                unsigned a0 = FU(E_s[wr + mt * 16 + gid][k0 + t4]);
                unsigned a1 = FU(E_s[wr + mt * 16 + gid + 8][k0 + t4]);
                unsigned a2 = FU(E_s[wr + mt * 16 + gid][k0 + t4 + 4]);
                unsigned a3 = FU(E_s[wr + mt * 16 + gid + 8][k0 + t4 + 4]);
#pragma unroll
                for (int nt = 0; nt < 4; nt++)
                    mma8(acc[mt][nt], a0, a1, a2, a3, b0[nt], b1[nt]);
            }
        }
    }
    float* ab = g_att + (size_t)n * CI * HW;
#pragma unroll
    for (int mt = 0; mt < 2; mt++)
#pragma unroll
        for (int nt = 0; nt < 4; nt++)
#pragma unroll
            for (int i = 0; i < 2; i++)
#pragma unroll
                for (int j = 0; j < 2; j++) {
                    int q = q0 + wr + mt * 16 + gid + i * 8;
                    int c = c0 + wc + nt * 8 + 2 * t4 + j;
                    ab[(size_t)c * HW + q] = acc[mt][nt][i * 2 + j];
                }
}

// ---------------------------------------------------------------------------
// K4: epilogue. att slab is exactly linear in (r*256+cc) per batch.
// ---------------------------------------------------------------------------
__global__ void k_out(const float* __restrict__ mask, const float* __restrict__ ref,
                      float* __restrict__ out) {
    const int total = NB * HW * (CI / 4);  // 2097152 float4 groups
    const int stride = gridDim.x * blockDim.x;
    for (int g = blockIdx.x * blockDim.x + threadIdx.x; g < total; g += stride) {
        int n = g >> 18;
        int rem = g & 262143;
        int r = rem >> 6;
        int c4 = (rem & 63) << 2;
        float4 a  = *(const float4*)(g_att + (size_t)n * CI * HW + (size_t)r * CI + c4);
        float4 rf = *(const float4*)(ref + ((size_t)n * HW + r) * CI + c4);
        float m = mask[n * HW + r];
        float4 e;
        e.x = m * a.x + (1.f - m) * rf.x;
        e.y = m * a.y + (1.f - m) * rf.y;
        e.z = m * a.z + (1.f - m) * rf.z;
        e.w = m * a.w + (1.f - m) * rf.w;
        size_t ob = ((size_t)n * HW + r) * (2 * CI);
        *(float4*)(out + ob + c4) = e;
        *(float4*)(out + ob + CI + c4) = a;
    }
}

extern "C" void kernel_launch(void* const* d_in, const int* in_sizes, int n_in,
                              void* d_out, int out_size) {
    const float* mask = (const float*)d_in[0];
    const float* F    = (const float*)d_in[1];
    const float* ref  = (const float*)d_in[2];
    const float* W    = (const float*)d_in[3];
    float* out = (float*)d_out;
    (void)in_sizes; (void)n_in; (void)out_size;

    cudaFuncSetAttribute(k_att, cudaFuncAttributeMaxDynamicSharedMemorySize, K3_SMEM);

    k_query<<<dim3(32, 8), 256>>>(F, W);
    k_rowsum<<<dim3(64, 8), 256>>>();
    k_att<<<dim3(32, 2, 8), 512, K3_SMEM>>>(F);
    k_out<<<2048, 256>>>(mask, ref, out);
}